// round 16
// baseline (speedup 1.0000x reference)
#include <cuda_runtime.h>
#include <cuda_fp16.h>
#include <cstdint>
#include <cstddef>

#define BB 4
#define TT 4096
#define DM 512
#define DH 64
#define BT (BB*TT)   // 16384

// q pre-scale: 0.125 * log2(e)
#define QSCALE 0.18033688011112042f

// ---------------- scratch (device globals; no allocation allowed) ----------
__device__ __half g_qh[BT*DH];
__device__ __half g_kh[BT*DH];
__device__ float  g_v[BT*DH];
__device__ __half g_vshT[(size_t)BB*DH*TT];   // transposed scaled v, fp16
__device__ float  g_colsum[BT];
__device__ __half g_E[(size_t)BB*TT*TT];      // masked exp scores, fp16

// ---------------- helpers ---------------------------------------------------
__device__ __forceinline__ float ex2f(float x) {
    float y;
    asm("ex2.approx.ftz.f32 %0, %1;" : "=f"(y) : "f"(x));
    return y;
}

__device__ __forceinline__ void mmah(float4& c, const uint32_t* a,
                                     uint32_t b0, uint32_t b1) {
    asm volatile(
        "mma.sync.aligned.m16n8k16.row.col.f32.f16.f16.f32 "
        "{%0,%1,%2,%3}, {%4,%5,%6,%7}, {%8,%9}, {%0,%1,%2,%3};"
        : "+f"(c.x), "+f"(c.y), "+f"(c.z), "+f"(c.w)
        : "r"(a[0]), "r"(a[1]), "r"(a[2]), "r"(a[3]), "r"(b0), "r"(b1));
}

__device__ __forceinline__ void ldm4(uint32_t* f, uint32_t addr) {
    asm volatile("ldmatrix.sync.aligned.m8n8.x4.shared.b16 {%0,%1,%2,%3}, [%4];"
        : "=r"(f[0]), "=r"(f[1]), "=r"(f[2]), "=r"(f[3]) : "r"(addr));
}

__device__ __forceinline__ void cp16(uint32_t saddr, const void* g) {
    asm volatile("cp.async.ca.shared.global [%0], [%1], 16;"
        :: "r"(saddr), "l"(g) : "memory");
}
__device__ __forceinline__ void cp16cg(uint32_t saddr, const void* g) {
    asm volatile("cp.async.cg.shared.global [%0], [%1], 16;"
        :: "r"(saddr), "l"(g) : "memory");
}
__device__ __forceinline__ void cpcommit() {
    asm volatile("cp.async.commit_group;" ::: "memory");
}
template<int N> __device__ __forceinline__ void cpwait() {
    asm volatile("cp.async.wait_group %0;" :: "n"(N) : "memory");
}
__device__ __forceinline__ void sts64(uint32_t addr, uint32_t u0, uint32_t u1) {
    asm volatile("st.shared.v2.u32 [%0], {%1,%2};" :: "r"(addr), "r"(u0), "r"(u1));
}
__device__ __forceinline__ uint32_t packh2(float lo, float hi) {
    __half2 h = __floats2half2_rn(lo, hi);
    return *(uint32_t*)&h;
}

// fp16 tiles: rows x 64 halfs, stride 144 B
#define HSB 144
#define HTILE (128*HSB)      // 18432 B
#define WTILE (64*HSB)       // 9216 B
// E tiles: 128 x 128 halfs, stride 272 B.  V tiles: 64 x 128, stride 272.
#define ESB 272
#define ETILE (128*ESB)      // 34816 B
#define VTILE (64*ESB)       // 17408 B

__device__ __forceinline__ void stage_h(uint32_t sbase, const __half* g) {
    for (int c = threadIdx.x; c < 1024; c += blockDim.x) {
        int r = c >> 3, ch = c & 7;
        cp16(sbase + r * HSB + ch * 16, g + (size_t)r * DH + ch * 8);
    }
}
__device__ __forceinline__ void stage_E(uint32_t sbase, const __half* g) {
    for (int c = threadIdx.x; c < 2048; c += blockDim.x) {
        int r = c >> 4, ch = c & 15;
        cp16cg(sbase + r * ESB + ch * 16, g + (size_t)r * TT + ch * 8);
    }
}
__device__ __forceinline__ void stage_V(uint32_t sbase, const __half* g) {
    for (int c = threadIdx.x; c < 1024; c += blockDim.x) {
        int r = c >> 4, ch = c & 15;
        cp16cg(sbase + r * ESB + ch * 16, g + (size_t)r * TT + ch * 8);
    }
}

// ===========================================================================
// K1: QKV projections, full fp16 MMA. q (pre-scaled), k -> fp16; v -> fp32.
// Also zeroes g_colsum (blockIdx.y == 0 CTAs).
// ===========================================================================
__global__ __launch_bounds__(256) void proj_kernel(
        const float* __restrict__ x,
        const float* __restrict__ Wq,
        const float* __restrict__ Wk,
        const float* __restrict__ Wv) {
    extern __shared__ char smemc[];
    const uint32_t s32 = (uint32_t)__cvta_generic_to_shared(smemc);
    const uint32_t hx = s32;
    const uint32_t hw = s32 + HTILE;

    const int row0 = blockIdx.x * 128;
    const float* W = (blockIdx.y == 0) ? Wq : (blockIdx.y == 1) ? Wk : Wv;

    const int tid = threadIdx.x, lane = tid & 31, w = tid >> 5;
    const int wm = w & 3, wn = w >> 2;
    const int g4 = lane >> 2, tc = lane & 3;

    // fold g_colsum zeroing into this kernel (grid.x == 128, 128*128 == BT)
    if (blockIdx.y == 0 && tid < 128)
        g_colsum[blockIdx.x * 128 + tid] = 0.f;

    const uint32_t aoff = ((lane & 15) * 72 + ((lane >> 4) << 3)) * 2;
    const uint32_t boff = (((lane & 7) + (((lane >> 4) & 1) << 3)) * 72
                           + (((lane >> 3) & 1) << 3)) * 2;

    float4 px[8], pw[4];
#pragma unroll
    for (int j = 0; j < 8; j++) {
        int f = tid + 256*j, r = f >> 4, c4 = f & 15;
        px[j] = *(const float4*)&x[(size_t)(row0 + r) * DM + c4 * 4];
    }
#pragma unroll
    for (int j = 0; j < 4; j++) {
        int f = tid + 256*j, n = f >> 4, c4 = f & 15;
        pw[j] = *(const float4*)&W[(size_t)n * DM + c4 * 4];
    }

    float4 acc[2][4];
#pragma unroll
    for (int i = 0; i < 2; i++)
#pragma unroll
        for (int j = 0; j < 4; j++) acc[i][j] = make_float4(0.f,0.f,0.f,0.f);

    for (int kc = 0; kc < 8; kc++) {
#pragma unroll
        for (int j = 0; j < 8; j++) {
            int f = tid + 256*j, r = f >> 4, c4 = f & 15;
            sts64(hx + r*HSB + c4*8, packh2(px[j].x, px[j].y), packh2(px[j].z, px[j].w));
        }
#pragma unroll
        for (int j = 0; j < 4; j++) {
            int f = tid + 256*j, n = f >> 4, c4 = f & 15;
            sts64(hw + n*HSB + c4*8, packh2(pw[j].x, pw[j].y), packh2(pw[j].z, pw[j].w));
        }
        __syncthreads();

        if (kc < 7) {
            const int ko = (kc + 1) * 64;
#pragma unroll
            for (int j = 0; j < 8; j++) {
                int f = tid + 256*j, r = f >> 4, c4 = f & 15;
                px[j] = *(const float4*)&x[(size_t)(row0 + r) * DM + ko + c4 * 4];
            }
#pragma unroll
            for (int j = 0; j < 4; j++) {
                int f = tid + 256*j, n = f >> 4, c4 = f & 15;
                pw[j] = *(const float4*)&W[(size_t)n * DM + ko + c4 * 4];
            }
        }

#pragma unroll
        for (int c4i = 0; c4i < 4; c4i++) {
            const int k16 = c4i * 16;
            uint32_t a0[4], a1[4];
            ldm4(a0, hx + (wm*32)      * HSB + k16*2 + aoff);
            ldm4(a1, hx + (wm*32 + 16) * HSB + k16*2 + aoff);
#pragma unroll
            for (int nt2 = 0; nt2 < 2; nt2++) {
                uint32_t bf[4];
                ldm4(bf, hw + (wn*32 + nt2*16) * HSB + k16*2 + boff);
                mmah(acc[0][nt2*2],   a0, bf[0], bf[1]);
                mmah(acc[0][nt2*2+1], a0, bf[2], bf[3]);
                mmah(acc[1][nt2*2],   a1, bf[0], bf[1]);
                mmah(acc[1][nt2*2+1], a1, bf[2], bf[3]);
            }
        }
        __syncthreads();
    }

    const float sc = (blockIdx.y == 0) ? QSCALE : 1.0f;
#pragma unroll
    for (int mt = 0; mt < 2; mt++)
#pragma unroll
        for (int nt2 = 0; nt2 < 2; nt2++)
#pragma unroll
            for (int p = 0; p < 2; p++) {
                int r = row0 + wm*32 + mt*16 + g4;
                int h = wn*32 + nt2*16 + p*8 + tc*2;
                float4 c = acc[mt][nt2*2 + p];
                if (blockIdx.y < 2) {
                    __half* oh = (blockIdx.y == 0) ? g_qh : g_kh;
                    *(__half2*)&oh[(size_t)r * DH + h]     = __floats2half2_rn(c.x*sc, c.y*sc);
                    *(__half2*)&oh[(size_t)(r+8) * DH + h] = __floats2half2_rn(c.z*sc, c.w*sc);
                } else {
                    *(float2*)&g_v[(size_t)r * DH + h]     = make_float2(c.x, c.y);
                    *(float2*)&g_v[(size_t)(r+8) * DH + h] = make_float2(c.z, c.w);
                }
            }
}

// ===========================================================================
// K2: persistent balanced colsum + E.  2112 jobs (b, sb, tidx),
// 264 CTAs x 8 contiguous jobs, k+q double-buffered, flush colsums on
// row change via smem-aggregated global atomics.
// ===========================================================================
#define CS_NJOBS_PER_B 528   // 32+31+...+1

__device__ __forceinline__ void cs_decode(int job, int& b, int& sb, int& tidx) {
    b = job / CS_NJOBS_PER_B;
    int r = job - b * CS_NJOBS_PER_B;
    // cum(s) = 32s - s(s-1)/2 ; find s with cum(s) <= r < cum(s+1)
    int s = (int)(32.5f - __fsqrt_rn(32.5f*32.5f - 2.f*(float)r));
    if (s < 0) s = 0; if (s > 31) s = 31;
    while (s < 31 && 32*(s+1) - ((s+1)*s)/2 <= r) s++;
    while (s > 0 && 32*s - (s*(s-1))/2 > r) s--;
    sb = s;
    tidx = s + (r - (32*s - (s*(s-1))/2));
}

__global__ __launch_bounds__(512, 2) void colsum_kernel() {
    const int job0 = blockIdx.x * 8;

    extern __shared__ char smemc[];
    const uint32_t s32 = (uint32_t)__cvta_generic_to_shared(smemc);
    const uint32_t kb[2] = { s32, s32 + HTILE };
    const uint32_t qb[2] = { s32 + 2*HTILE, s32 + 3*HTILE };
    float* colbuf = (float*)(smemc + 4*HTILE);   // [128]

    const int tid = threadIdx.x, lane = tid & 31, w = tid >> 5;
    const int wm = w & 7, wn = w >> 3;
    const int g4 = lane >> 2, tc = lane & 3;

    const uint32_t aoff = ((lane & 15) * 72 + ((lane >> 4) << 3)) * 2;
    const uint32_t boff = (((lane & 7) + (((lane >> 4) & 1) << 3)) * 72
                           + (((lane >> 3) & 1) << 3)) * 2;

    if (tid < 128) colbuf[tid] = 0.f;

    int cb, csb, ctidx;
    cs_decode(job0, cb, csb, ctidx);
    stage_h(kb[0], g_kh + (size_t)(cb*TT + csb*128) * DH);
    stage_h(qb[0], g_qh + (size_t)(cb*TT + ctidx*128) * DH);
    cpcommit();

    float colp[8][2];
#pragma unroll
    for (int nt = 0; nt < 8; nt++) { colp[nt][0] = 0.f; colp[nt][1] = 0.f; }

    int bi = 0;
    for (int j = 0; j < 8; j++, bi ^= 1) {
        int nb = cb, nsb = csb, ntidx = ctidx;
        if (j + 1 < 8) {
            cs_decode(job0 + j + 1, nb, nsb, ntidx);
            stage_h(kb[bi^1], g_kh + (size_t)(nb*TT + nsb*128) * DH);
            stage_h(qb[bi^1], g_qh + (size_t)(nb*TT + ntidx*128) * DH);
            cpcommit();
            cpwait<1>();
        } else cpwait<0>();
        __syncthreads();

        float4 acc[8];
#pragma unroll
        for (int i = 0; i < 8; i++) acc[i] = make_float4(0.f,0.f,0.f,0.f);

#pragma unroll
        for (int c4 = 0; c4 < 4; c4++) {
            const int kc = c4 * 16;
            uint32_t a[4];
            ldm4(a, qb[bi] + (wm*16) * HSB + kc*2 + aoff);
#pragma unroll
            for (int nt2 = 0; nt2 < 4; nt2++) {
                uint32_t bf[4];
                ldm4(bf, kb[bi] + (wn*64 + nt2*16) * HSB + kc*2 + boff);
                mmah(acc[nt2*2],   a, bf[0], bf[1]);
                mmah(acc[nt2*2+1], a, bf[2], bf[3]);
            }
        }

        const bool diag = (ctidx == csb);
        const int s0 = csb * 128;
        const int t = ctidx * 128 + wm*16 + g4;

#pragma unroll
        for (int nt = 0; nt < 8; nt++) {
            float4 c = acc[nt];
            float e0 = ex2f(c.x), e1 = ex2f(c.y);
            float e2 = ex2f(c.z), e3 = ex2f(c.w);
            int s = s0 + wn*64 + nt*8 + tc*2;
            if (diag) {
                e0 = (s     <= t    ) ? e0 : 0.f;
                e1 = (s + 1 <= t    ) ? e1 : 0.f;
                e2 = (s     <= t + 8) ? e2 : 0.f;
                e3 = (s + 1 <= t + 8) ? e3 : 0.f;
            }
            *(__half2*)&g_E[((size_t)(cb*TT + t))*TT + s]     = __floats2half2_rn(e0, e1);
            *(__half2*)&g_E[((size_t)(cb*TT + t + 8))*TT + s] = __floats2half2_rn(e2, e3);
            colp[nt][0] += e0 + e2;
            colp[nt][1] += e1 + e3;
        }

        // flush column sums when the (b, sb) row changes or at the end
        if (j + 1 == 8 || nb != cb || nsb != csb) {
#pragma unroll
            for (int nt = 0; nt < 8; nt++)
#pragma unroll
                for (int par = 0; par < 2; par++) {
                    float vsum = colp[nt][par];
                    vsum += __shfl_xor_sync(0xffffffffu, vsum, 4);
                    vsum += __shfl_xor_sync(0xffffffffu, vsum, 8);
                    vsum += __shfl_xor_sync(0xffffffffu, vsum, 16);
                    if (g4 == 0)
                        atomicAdd(&colbuf[wn*64 + nt*8 + tc*2 + par], vsum);
                }
            __syncthreads();
            if (tid < 128) {
                atomicAdd(&g_colsum[cb*TT + csb*128 + tid], colbuf[tid]);
                colbuf[tid] = 0.f;
            }
#pragma unroll
            for (int nt = 0; nt < 8; nt++) { colp[nt][0] = 0.f; colp[nt][1] = 0.f; }
        }
        __syncthreads();
        cb = nb; csb = nsb; ctidx = ntidx;
    }
}

// ===========================================================================
// K3: zero out + vshT (reads g_colsum directly).  grid (TT/64, BB), 256 thr.
// ===========================================================================
__global__ __launch_bounds__(256) void vshT_kernel(float* __restrict__ out) {
    __shared__ float tile[64][65];
    __shared__ float cssm[64];
    const int s0 = blockIdx.x * 64, b = blockIdx.y;

    // zero this CTA's slice of out
    {
        float4* o4 = (float4*)(out + ((size_t)b*TT + s0) * DH);
        for (int i = threadIdx.x; i < 1024; i += 256)
            o4[i] = make_float4(0.f,0.f,0.f,0.f);
    }

    if (threadIdx.x < 64)
        cssm[threadIdx.x] = g_colsum[b*TT + s0 + threadIdx.x];
    __syncthreads();

    for (int idx = threadIdx.x; idx < 4096; idx += 256) {
        int s = idx >> 6, h = idx & 63;
        tile[s][h] = g_v[(size_t)(b*TT + s0 + s) * DH + h] / cssm[s];
    }
    __syncthreads();
    for (int idx = threadIdx.x; idx < 2048; idx += 256) {
        int h = idx >> 5, sp = idx & 31;
        *(__half2*)&g_vshT[((size_t)(b*DH + h)) * TT + s0 + sp*2] =
            __floats2half2_rn(tile[sp*2][h], tile[sp*2+1][h]);
    }
}

// ===========================================================================
// K4: persistent balanced AV (round-15 proven).
// ===========================================================================
#define NJOBS_PER_B 528
#define JOBS_PER_CTA 8

__device__ __forceinline__ void decode_job(int job, int& b, int& tb, int& sidx) {
    b = job / NJOBS_PER_B;
    int r = job - b * NJOBS_PER_B;
    int t = (int)((__fsqrt_rn(8.f * (float)r + 1.f) - 1.f) * 0.5f);
    while ((t + 1) * (t + 2) / 2 <= r) t++;
    while (t * (t + 1) / 2 > r) t--;
    tb = t;
    sidx = r - t * (t + 1) / 2;
}

__global__ __launch_bounds__(512, 2) void av_kernel(float* __restrict__ out) {
    const int job0 = blockIdx.x * JOBS_PER_CTA;

    extern __shared__ char smemc[];
    const uint32_t s32 = (uint32_t)__cvta_generic_to_shared(smemc);
    const uint32_t eb[2] = { s32, s32 + ETILE };
    const uint32_t vb[2] = { s32 + 2*ETILE, s32 + 2*ETILE + VTILE };

    const int tid = threadIdx.x, lane = tid & 31, w = tid >> 5;
    const int wm = w & 7, wn = w >> 3;
    const int g4 = lane >> 2, tc = lane & 3;

    const uint32_t aoff = (lane & 15) * ESB + ((lane >> 4) << 4);
    const uint32_t boff = ((lane & 7) + (((lane >> 4) & 1) << 3)) * ESB
                        + (((lane >> 3) & 1) << 4);

    int cb, ctb, csidx;
    decode_job(job0, cb, ctb, csidx);
    stage_E(eb[0], g_E + ((size_t)(cb*TT + ctb*128)) * TT + csidx*128);
    stage_V(vb[0], g_vshT + (size_t)cb * DH * TT + csidx*128);
    cpcommit();

    float4 oacc[4];
#pragma unroll
    for (int n = 0; n < 4; n++) oacc[n] = make_float4(0.f,0.f,0.f,0.f);

    int bi = 0;
    for (int j = 0; j < JOBS_PER_CTA; j++, bi ^= 1) {
        int nb = cb, ntb = ctb, nsidx = csidx;
        if (j + 1 < JOBS_PER_CTA) {
            decode_job(job0 + j + 1, nb, ntb, nsidx);
            stage_E(eb[bi^1], g_E + ((size_t)(nb*TT + ntb*128)) * TT + nsidx*128);
            stage_V(vb[bi^1], g_vshT + (size_t)nb * DH * TT + nsidx*128);
            cpcommit();
            cpwait<1>();
        } else cpwait<0>();
        __syncthreads();

#pragma unroll
        for (int c8 = 0; c8 < 8; c8++) {
            const int kc = c8 * 16;
            uint32_t a[4];
            ldm4(a, eb[bi] + (wm*16) * ESB + kc*2 + aoff);
#pragma unroll
            for (int nt2 = 0; nt2 < 2; nt2++) {
                uint32_t bf[4];
                ldm4(bf, vb[bi] + (wn*32 + nt2*16) * ESB + kc*2 + boff);
                mmah(oacc[nt2*2],   a, bf[0], bf[1]);
                mmah(oacc[nt2*2+1], a, bf[2], bf[3]);
            }
        }
        __syncthreads();

        if (j + 1 == JOBS_PER_CTA || nb != cb || ntb != ctb) {
            const size_t r = (size_t)(cb*TT + ctb*128 + wm*16 + g4);
#pragma unroll
            for (int n = 0; n < 4; n++) {
                int h = wn*32 + n*8 + tc*2;
                atomicAdd(&out[r * DH + h],           oacc[n].x);
                atomicAdd(&out[r * DH + h + 1],       oacc[n].y);
                atomicAdd(&out[(r + 8) * DH + h],     oacc[n].z);
                atomicAdd(&out[(r + 8) * DH + h + 1], oacc[n].w);
            }
#pragma unroll
            for (int n = 0; n < 4; n++) oacc[n] = make_float4(0.f,0.f,0.f,0.f);
        }
        cb = nb; ctb = ntb; csidx = nsidx;
    }
}

// ===========================================================================
// launch
// ===========================================================================
extern "C" void kernel_launch(void* const* d_in, const int* in_sizes, int n_in,
                              void* d_out, int out_size) {
    const float* x  = (const float*)d_in[0];
    const float* Wq = (const float*)d_in[1];
    const float* Wk = (const float*)d_in[2];
    const float* Wv = (const float*)d_in[3];
    float* out = (float*)d_out;

    const int smem_proj   = HTILE + WTILE;            // 27648
    const int smem_colsum = 4*HTILE + 512;            // 74240
    const int smem_av     = 2*ETILE + 2*VTILE;        // 104448

    cudaFuncSetAttribute(proj_kernel,   cudaFuncAttributeMaxDynamicSharedMemorySize, smem_proj);
    cudaFuncSetAttribute(colsum_kernel, cudaFuncAttributeMaxDynamicSharedMemorySize, smem_colsum);
    cudaFuncSetAttribute(av_kernel,     cudaFuncAttributeMaxDynamicSharedMemorySize, smem_av);

    proj_kernel<<<dim3(BT / 128, 3), 256, smem_proj>>>(x, Wq, Wk, Wv);
    colsum_kernel<<<264, 512, smem_colsum>>>();
    vshT_kernel<<<dim3(TT / 64, BB), 256>>>(out);
    av_kernel<<<264, 512, smem_av>>>(out);
}

// round 17
// speedup vs baseline: 1.4799x; 1.4799x over previous
#include <cuda_runtime.h>
#include <cuda_fp16.h>
#include <cstdint>
#include <cstddef>

#define BB 4
#define TT 4096
#define DM 512
#define DH 64
#define BT (BB*TT)   // 16384

// q pre-scale: 0.125 * log2(e)
#define QSCALE 0.18033688011112042f

// ---------------- scratch (device globals; no allocation allowed) ----------
__device__ __half g_qh[BT*DH];
__device__ __half g_kh[BT*DH];
__device__ float  g_v[BT*DH];
__device__ __half g_vshT[(size_t)BB*DH*TT];   // transposed scaled v, fp16
__device__ float  g_cs_part[BB*32*8*128];     // per (b,sb,strip) colsum partials
__device__ __half g_E[(size_t)BB*TT*TT];      // masked exp scores, fp16

// ---------------- helpers ---------------------------------------------------
__device__ __forceinline__ float ex2f(float x) {
    float y;
    asm("ex2.approx.ftz.f32 %0, %1;" : "=f"(y) : "f"(x));
    return y;
}

__device__ __forceinline__ void mmah(float4& c, const uint32_t* a,
                                     uint32_t b0, uint32_t b1) {
    asm volatile(
        "mma.sync.aligned.m16n8k16.row.col.f32.f16.f16.f32 "
        "{%0,%1,%2,%3}, {%4,%5,%6,%7}, {%8,%9}, {%0,%1,%2,%3};"
        : "+f"(c.x), "+f"(c.y), "+f"(c.z), "+f"(c.w)
        : "r"(a[0]), "r"(a[1]), "r"(a[2]), "r"(a[3]), "r"(b0), "r"(b1));
}

__device__ __forceinline__ void ldm4(uint32_t* f, uint32_t addr) {
    asm volatile("ldmatrix.sync.aligned.m8n8.x4.shared.b16 {%0,%1,%2,%3}, [%4];"
        : "=r"(f[0]), "=r"(f[1]), "=r"(f[2]), "=r"(f[3]) : "r"(addr));
}

__device__ __forceinline__ void cp16(uint32_t saddr, const void* g) {
    asm volatile("cp.async.ca.shared.global [%0], [%1], 16;"
        :: "r"(saddr), "l"(g) : "memory");
}
__device__ __forceinline__ void cp16cg(uint32_t saddr, const void* g) {
    asm volatile("cp.async.cg.shared.global [%0], [%1], 16;"
        :: "r"(saddr), "l"(g) : "memory");
}
__device__ __forceinline__ void cpcommit() {
    asm volatile("cp.async.commit_group;" ::: "memory");
}
template<int N> __device__ __forceinline__ void cpwait() {
    asm volatile("cp.async.wait_group %0;" :: "n"(N) : "memory");
}
__device__ __forceinline__ void sts64(uint32_t addr, uint32_t u0, uint32_t u1) {
    asm volatile("st.shared.v2.u32 [%0], {%1,%2};" :: "r"(addr), "r"(u0), "r"(u1));
}
__device__ __forceinline__ uint32_t packh2(float lo, float hi) {
    __half2 h = __floats2half2_rn(lo, hi);
    return *(uint32_t*)&h;
}

// fp16 tiles: rows x 64 halfs, stride 144 B
#define HSB 144
#define HTILE (128*HSB)      // 18432 B
#define WTILE (64*HSB)       // 9216 B
// E tiles: 128 x 128 halfs, stride 272 B.  V tiles: 64 x 128, stride 272.
#define ESB 272
#define ETILE (128*ESB)      // 34816 B
#define VTILE (64*ESB)       // 17408 B

__device__ __forceinline__ void stage_h(uint32_t sbase, const __half* g) {
    for (int c = threadIdx.x; c < 1024; c += blockDim.x) {
        int r = c >> 3, ch = c & 7;
        cp16(sbase + r * HSB + ch * 16, g + (size_t)r * DH + ch * 8);
    }
}
__device__ __forceinline__ void stage_E(uint32_t sbase, const __half* g) {
    for (int c = threadIdx.x; c < 2048; c += blockDim.x) {
        int r = c >> 4, ch = c & 15;
        cp16cg(sbase + r * ESB + ch * 16, g + (size_t)r * TT + ch * 8);
    }
}
__device__ __forceinline__ void stage_V(uint32_t sbase, const __half* g) {
    for (int c = threadIdx.x; c < 1024; c += blockDim.x) {
        int r = c >> 4, ch = c & 15;
        cp16cg(sbase + r * ESB + ch * 16, g + (size_t)r * TT + ch * 8);
    }
}

// ===========================================================================
// K1: QKV projections, full fp16 MMA. q (pre-scaled), k -> fp16; v -> fp32.
// ===========================================================================
__global__ __launch_bounds__(256) void proj_kernel(
        const float* __restrict__ x,
        const float* __restrict__ Wq,
        const float* __restrict__ Wk,
        const float* __restrict__ Wv) {
    extern __shared__ char smemc[];
    const uint32_t s32 = (uint32_t)__cvta_generic_to_shared(smemc);
    const uint32_t hx = s32;
    const uint32_t hw = s32 + HTILE;

    const int row0 = blockIdx.x * 128;
    const float* W = (blockIdx.y == 0) ? Wq : (blockIdx.y == 1) ? Wk : Wv;

    const int tid = threadIdx.x, lane = tid & 31, w = tid >> 5;
    const int wm = w & 3, wn = w >> 2;
    const int g4 = lane >> 2, tc = lane & 3;

    const uint32_t aoff = ((lane & 15) * 72 + ((lane >> 4) << 3)) * 2;
    const uint32_t boff = (((lane & 7) + (((lane >> 4) & 1) << 3)) * 72
                           + (((lane >> 3) & 1) << 3)) * 2;

    float4 px[8], pw[4];
#pragma unroll
    for (int j = 0; j < 8; j++) {
        int f = tid + 256*j, r = f >> 4, c4 = f & 15;
        px[j] = *(const float4*)&x[(size_t)(row0 + r) * DM + c4 * 4];
    }
#pragma unroll
    for (int j = 0; j < 4; j++) {
        int f = tid + 256*j, n = f >> 4, c4 = f & 15;
        pw[j] = *(const float4*)&W[(size_t)n * DM + c4 * 4];
    }

    float4 acc[2][4];
#pragma unroll
    for (int i = 0; i < 2; i++)
#pragma unroll
        for (int j = 0; j < 4; j++) acc[i][j] = make_float4(0.f,0.f,0.f,0.f);

    for (int kc = 0; kc < 8; kc++) {
#pragma unroll
        for (int j = 0; j < 8; j++) {
            int f = tid + 256*j, r = f >> 4, c4 = f & 15;
            sts64(hx + r*HSB + c4*8, packh2(px[j].x, px[j].y), packh2(px[j].z, px[j].w));
        }
#pragma unroll
        for (int j = 0; j < 4; j++) {
            int f = tid + 256*j, n = f >> 4, c4 = f & 15;
            sts64(hw + n*HSB + c4*8, packh2(pw[j].x, pw[j].y), packh2(pw[j].z, pw[j].w));
        }
        __syncthreads();

        if (kc < 7) {
            const int ko = (kc + 1) * 64;
#pragma unroll
            for (int j = 0; j < 8; j++) {
                int f = tid + 256*j, r = f >> 4, c4 = f & 15;
                px[j] = *(const float4*)&x[(size_t)(row0 + r) * DM + ko + c4 * 4];
            }
#pragma unroll
            for (int j = 0; j < 4; j++) {
                int f = tid + 256*j, n = f >> 4, c4 = f & 15;
                pw[j] = *(const float4*)&W[(size_t)n * DM + ko + c4 * 4];
            }
        }

#pragma unroll
        for (int c4i = 0; c4i < 4; c4i++) {
            const int k16 = c4i * 16;
            uint32_t a0[4], a1[4];
            ldm4(a0, hx + (wm*32)      * HSB + k16*2 + aoff);
            ldm4(a1, hx + (wm*32 + 16) * HSB + k16*2 + aoff);
#pragma unroll
            for (int nt2 = 0; nt2 < 2; nt2++) {
                uint32_t bf[4];
                ldm4(bf, hw + (wn*32 + nt2*16) * HSB + k16*2 + boff);
                mmah(acc[0][nt2*2],   a0, bf[0], bf[1]);
                mmah(acc[0][nt2*2+1], a0, bf[2], bf[3]);
                mmah(acc[1][nt2*2],   a1, bf[0], bf[1]);
                mmah(acc[1][nt2*2+1], a1, bf[2], bf[3]);
            }
        }
        __syncthreads();
    }

    const float sc = (blockIdx.y == 0) ? QSCALE : 1.0f;
#pragma unroll
    for (int mt = 0; mt < 2; mt++)
#pragma unroll
        for (int nt2 = 0; nt2 < 2; nt2++)
#pragma unroll
            for (int p = 0; p < 2; p++) {
                int r = row0 + wm*32 + mt*16 + g4;
                int h = wn*32 + nt2*16 + p*8 + tc*2;
                float4 c = acc[mt][nt2*2 + p];
                if (blockIdx.y < 2) {
                    __half* oh = (blockIdx.y == 0) ? g_qh : g_kh;
                    *(__half2*)&oh[(size_t)r * DH + h]     = __floats2half2_rn(c.x*sc, c.y*sc);
                    *(__half2*)&oh[(size_t)(r+8) * DH + h] = __floats2half2_rn(c.z*sc, c.w*sc);
                } else {
                    *(float2*)&g_v[(size_t)r * DH + h]     = make_float2(c.x, c.y);
                    *(float2*)&g_v[(size_t)(r+8) * DH + h] = make_float2(c.z, c.w);
                }
            }
}

// ===========================================================================
// K2: colsum partials + E materialization.  512 threads, warp = 16t x 64s.
// grid (32 sb, BB, 8 strips). k staged once; q TRIPLE-buffered (depth 3).
// ===========================================================================
__global__ __launch_bounds__(512, 2) void colsum_kernel() {
    const int sb = blockIdx.x, b = blockIdx.y, strip = blockIdx.z;
    const int t_i0 = sb + strip;
    if (t_i0 >= 32) return;
    const int ntiles = (32 - t_i0 + 7) >> 3;   // 1..4

    extern __shared__ char smemc[];
    const uint32_t s32 = (uint32_t)__cvta_generic_to_shared(smemc);
    const uint32_t hk = s32;
    const uint32_t hq[3] = { s32 + HTILE, s32 + 2*HTILE, s32 + 3*HTILE };
    float* colbuf = (float*)(smemc + 4*HTILE);   // [128]

    const int tid = threadIdx.x, lane = tid & 31, w = tid >> 5;
    const int wm = w & 7, wn = w >> 3;
    const int g4 = lane >> 2, tc = lane & 3;
    const int s0 = sb * 128;

    if (tid < 128) colbuf[tid] = 0.f;

    const uint32_t aoff = ((lane & 15) * 72 + ((lane >> 4) << 3)) * 2;
    const uint32_t boff = (((lane & 7) + (((lane >> 4) & 1) << 3)) * 72
                           + (((lane >> 3) & 1) << 3)) * 2;

    // group 0: k + q0 ; group 1: q1
    stage_h(hk, g_kh + (size_t)(b*TT + s0) * DH);
    stage_h(hq[0], g_qh + (size_t)(b*TT + t_i0*128) * DH);
    cpcommit();
    if (ntiles > 1) {
        stage_h(hq[1], g_qh + (size_t)(b*TT + (t_i0+8)*128) * DH);
        cpcommit();
    }

    float colp[8][2];
#pragma unroll
    for (int nt = 0; nt < 8; nt++) { colp[nt][0] = 0.f; colp[nt][1] = 0.f; }

    for (int i = 0; i < ntiles; i++) {
        const int tidx = t_i0 + i*8;
        if (i + 2 < ntiles) {
            stage_h(hq[(i+2)%3], g_qh + (size_t)(b*TT + (tidx+16)*128) * DH);
            cpcommit();
            cpwait<2>();
        } else if (i + 1 < ntiles) {
            cpwait<1>();
        } else {
            cpwait<0>();
        }
        __syncthreads();

        const uint32_t q = hq[i % 3];
        float4 acc[8];
#pragma unroll
        for (int j = 0; j < 8; j++) acc[j] = make_float4(0.f,0.f,0.f,0.f);

#pragma unroll
        for (int c4 = 0; c4 < 4; c4++) {
            const int kc = c4 * 16;
            uint32_t a[4];
            ldm4(a, q + (wm*16) * HSB + kc*2 + aoff);
#pragma unroll
            for (int nt2 = 0; nt2 < 4; nt2++) {
                uint32_t bf[4];
                ldm4(bf, hk + (wn*64 + nt2*16) * HSB + kc*2 + boff);
                mmah(acc[nt2*2],   a, bf[0], bf[1]);
                mmah(acc[nt2*2+1], a, bf[2], bf[3]);
            }
        }

        const bool diag = (tidx == sb);
        const int t = tidx * 128 + wm*16 + g4;

#pragma unroll
        for (int nt = 0; nt < 8; nt++) {
            float4 c = acc[nt];
            float e0 = ex2f(c.x), e1 = ex2f(c.y);
            float e2 = ex2f(c.z), e3 = ex2f(c.w);
            int s = s0 + wn*64 + nt*8 + tc*2;
            if (diag) {
                e0 = (s     <= t    ) ? e0 : 0.f;
                e1 = (s + 1 <= t    ) ? e1 : 0.f;
                e2 = (s     <= t + 8) ? e2 : 0.f;
                e3 = (s + 1 <= t + 8) ? e3 : 0.f;
            }
            *(__half2*)&g_E[((size_t)(b*TT + t))*TT + s]     = __floats2half2_rn(e0, e1);
            *(__half2*)&g_E[((size_t)(b*TT + t + 8))*TT + s] = __floats2half2_rn(e2, e3);
            colp[nt][0] += e0 + e2;
            colp[nt][1] += e1 + e3;
        }
        __syncthreads();
    }

#pragma unroll
    for (int nt = 0; nt < 8; nt++)
#pragma unroll
        for (int par = 0; par < 2; par++) {
            float vsum = colp[nt][par];
            vsum += __shfl_xor_sync(0xffffffffu, vsum, 4);
            vsum += __shfl_xor_sync(0xffffffffu, vsum, 8);
            vsum += __shfl_xor_sync(0xffffffffu, vsum, 16);
            if (g4 == 0)
                atomicAdd(&colbuf[wn*64 + nt*8 + tc*2 + par], vsum);
        }
    __syncthreads();

    if (tid < 128)
        g_cs_part[((b*32 + sb)*8 + strip)*128 + tid] = colbuf[tid];
}

// ===========================================================================
// K3: zero out + reduce colsum partials + vshT.  grid (TT/64, BB), 256 thr.
// ===========================================================================
__global__ __launch_bounds__(256) void vshT_kernel(float* __restrict__ out) {
    __shared__ float tile[64][65];
    __shared__ float cssm[64];
    const int s0 = blockIdx.x * 64, b = blockIdx.y;

    // zero this CTA's slice of out
    {
        float4* o4 = (float4*)(out + ((size_t)b*TT + s0) * DH);
        for (int i = threadIdx.x; i < 1024; i += 256)
            o4[i] = make_float4(0.f,0.f,0.f,0.f);
    }

    if (threadIdx.x < 64) {
        int sb = s0 >> 7, idx = (s0 & 127) + threadIdx.x;
        const float* part = g_cs_part + ((b*32 + sb)*8)*128 + idx;
        float cs = 0.f;
#pragma unroll
        for (int j = 0; j < 8; j++) cs += part[j*128];
        cssm[threadIdx.x] = cs;
    }
    __syncthreads();

    for (int idx = threadIdx.x; idx < 4096; idx += 256) {
        int s = idx >> 6, h = idx & 63;
        tile[s][h] = g_v[(size_t)(b*TT + s0 + s) * DH + h] / cssm[s];
    }
    __syncthreads();
    for (int idx = threadIdx.x; idx < 2048; idx += 256) {
        int h = idx >> 5, sp = idx & 31;
        *(__half2*)&g_vshT[((size_t)(b*DH + h)) * TT + s0 + sp*2] =
            __floats2half2_rn(tile[sp*2][h], tile[sp*2+1][h]);
    }
}

// ===========================================================================
// K4: persistent balanced AV (round-15 proven, unchanged).
// ===========================================================================
#define NJOBS_PER_B 528
#define JOBS_PER_CTA 8

__device__ __forceinline__ void decode_job(int job, int& b, int& tb, int& sidx) {
    b = job / NJOBS_PER_B;
    int r = job - b * NJOBS_PER_B;
    int t = (int)((__fsqrt_rn(8.f * (float)r + 1.f) - 1.f) * 0.5f);
    while ((t + 1) * (t + 2) / 2 <= r) t++;
    while (t * (t + 1) / 2 > r) t--;
    tb = t;
    sidx = r - t * (t + 1) / 2;
}

__global__ __launch_bounds__(512, 2) void av_kernel(float* __restrict__ out) {
    const int job0 = blockIdx.x * JOBS_PER_CTA;

    extern __shared__ char smemc[];
    const uint32_t s32 = (uint32_t)__cvta_generic_to_shared(smemc);
    const uint32_t eb[2] = { s32, s32 + ETILE };
    const uint32_t vb[2] = { s32 + 2*ETILE, s32 + 2*ETILE + VTILE };

    const int tid = threadIdx.x, lane = tid & 31, w = tid >> 5;
    const int wm = w & 7, wn = w >> 3;
    const int g4 = lane >> 2, tc = lane & 3;

    const uint32_t aoff = (lane & 15) * ESB + ((lane >> 4) << 4);
    const uint32_t boff = ((lane & 7) + (((lane >> 4) & 1) << 3)) * ESB
                        + (((lane >> 3) & 1) << 4);

    int cb, ctb, csidx;
    decode_job(job0, cb, ctb, csidx);
    stage_E(eb[0], g_E + ((size_t)(cb*TT + ctb*128)) * TT + csidx*128);
    stage_V(vb[0], g_vshT + (size_t)cb * DH * TT + csidx*128);
    cpcommit();

    float4 oacc[4];
#pragma unroll
    for (int n = 0; n < 4; n++) oacc[n] = make_float4(0.f,0.f,0.f,0.f);

    int bi = 0;
    for (int j = 0; j < JOBS_PER_CTA; j++, bi ^= 1) {
        int nb = cb, ntb = ctb, nsidx = csidx;
        if (j + 1 < JOBS_PER_CTA) {
            decode_job(job0 + j + 1, nb, ntb, nsidx);
            stage_E(eb[bi^1], g_E + ((size_t)(nb*TT + ntb*128)) * TT + nsidx*128);
            stage_V(vb[bi^1], g_vshT + (size_t)nb * DH * TT + nsidx*128);
            cpcommit();
            cpwait<1>();
        } else cpwait<0>();
        __syncthreads();

#pragma unroll
        for (int c8 = 0; c8 < 8; c8++) {
            const int kc = c8 * 16;
            uint32_t a[4];
            ldm4(a, eb[bi] + (wm*16) * ESB + kc*2 + aoff);
#pragma unroll
            for (int nt2 = 0; nt2 < 2; nt2++) {
                uint32_t bf[4];
                ldm4(bf, vb[bi] + (wn*32 + nt2*16) * ESB + kc*2 + boff);
                mmah(oacc[nt2*2],   a, bf[0], bf[1]);
                mmah(oacc[nt2*2+1], a, bf[2], bf[3]);
            }
        }
        __syncthreads();

        if (j + 1 == JOBS_PER_CTA || nb != cb || ntb != ctb) {
            const size_t r = (size_t)(cb*TT + ctb*128 + wm*16 + g4);
#pragma unroll
            for (int n = 0; n < 4; n++) {
                int h = wn*32 + n*8 + tc*2;
                atomicAdd(&out[r * DH + h],           oacc[n].x);
                atomicAdd(&out[r * DH + h + 1],       oacc[n].y);
                atomicAdd(&out[(r + 8) * DH + h],     oacc[n].z);
                atomicAdd(&out[(r + 8) * DH + h + 1], oacc[n].w);
            }
#pragma unroll
            for (int n = 0; n < 4; n++) oacc[n] = make_float4(0.f,0.f,0.f,0.f);
        }
        cb = nb; ctb = ntb; csidx = nsidx;
    }
}

// ===========================================================================
// launch
// ===========================================================================
extern "C" void kernel_launch(void* const* d_in, const int* in_sizes, int n_in,
                              void* d_out, int out_size) {
    const float* x  = (const float*)d_in[0];
    const float* Wq = (const float*)d_in[1];
    const float* Wk = (const float*)d_in[2];
    const float* Wv = (const float*)d_in[3];
    float* out = (float*)d_out;

    const int smem_proj   = HTILE + WTILE;            // 27648
    const int smem_colsum = 4*HTILE + 512;            // 74240
    const int smem_av     = 2*ETILE + 2*VTILE;        // 104448

    cudaFuncSetAttribute(proj_kernel,   cudaFuncAttributeMaxDynamicSharedMemorySize, smem_proj);
    cudaFuncSetAttribute(colsum_kernel, cudaFuncAttributeMaxDynamicSharedMemorySize, smem_colsum);
    cudaFuncSetAttribute(av_kernel,     cudaFuncAttributeMaxDynamicSharedMemorySize, smem_av);

    proj_kernel<<<dim3(BT / 128, 3), 256, smem_proj>>>(x, Wq, Wk, Wv);
    colsum_kernel<<<dim3(32, BB, 8), 512, smem_colsum>>>();
    vshT_kernel<<<dim3(TT / 64, BB), 256>>>(out);
    av_kernel<<<264, 512, smem_av>>>(out);
}